// round 1
// baseline (speedup 1.0000x reference)
#include <cuda_runtime.h>
#include <math.h>

// Problem constants
#define TOKENS 8192      // 4 * 2048
#define BATCH  4
#define SEQ    2048
#define DIMM   1024
#define QKVN   3072
#define HEADS  16
#define DH     64
#define LDP    68        // padded smem row stride (floats), 16B-aligned, conflict-reduced

// Scratch (no cudaMalloc allowed) — ~128 MB of __device__ globals
__device__ float g_qkv[(size_t)TOKENS * QKVN];   // [token][3*1024]: q | k | v
__device__ float g_attn[(size_t)TOKENS * DIMM];  // attention output, [token][h*64+d]

// ----------------------------------------------------------------------------
// Generic fp32 SGEMM: C[M,N] = A[M,K] @ B[K,N] (+ bias[N] if bias != nullptr)
// BM=BN=128, BK=8, 256 threads, 8x8 per-thread microtile.
// Requires M%128==0, N%128==0, K%8==0, K%4==0, N%4==0 (true for all our shapes).
// ----------------------------------------------------------------------------
__global__ __launch_bounds__(256) void sgemm128(const float* __restrict__ A,
                                                const float* __restrict__ B,
                                                const float* __restrict__ bias,
                                                float* __restrict__ C,
                                                int M, int N, int K)
{
    __shared__ float As[8][128];   // [k][m] (transposed)
    __shared__ float Bs[8][128];   // [k][n]

    const int tid  = threadIdx.x;
    const int trow = tid >> 4;          // 0..15
    const int tcol = tid & 15;          // 0..15
    const int m0   = blockIdx.y * 128;
    const int n0   = blockIdx.x * 128;

    const int arow = tid >> 1;          // 0..127
    const int acol = (tid & 1) << 2;    // 0 or 4
    const int brow = tid >> 5;          // 0..7
    const int bcol = (tid & 31) << 2;   // 0..124

    const float* Ag = A + (size_t)(m0 + arow) * K + acol;
    const float* Bg = B + (size_t)brow * N + n0 + bcol;

    float acc[8][8];
#pragma unroll
    for (int i = 0; i < 8; i++)
#pragma unroll
        for (int j = 0; j < 8; j++) acc[i][j] = 0.0f;

    for (int k0 = 0; k0 < K; k0 += 8) {
        float4 av = *(const float4*)(Ag + k0);
        float4 bv = *(const float4*)(Bg + (size_t)k0 * N);

        As[acol + 0][arow] = av.x;
        As[acol + 1][arow] = av.y;
        As[acol + 2][arow] = av.z;
        As[acol + 3][arow] = av.w;
        *(float4*)&Bs[brow][bcol] = bv;
        __syncthreads();

#pragma unroll
        for (int kk = 0; kk < 8; kk++) {
            float4 a0 = *(const float4*)&As[kk][trow * 8];
            float4 a1 = *(const float4*)&As[kk][trow * 8 + 4];
            float4 b0 = *(const float4*)&Bs[kk][tcol * 8];
            float4 b1 = *(const float4*)&Bs[kk][tcol * 8 + 4];
            float ar[8] = {a0.x, a0.y, a0.z, a0.w, a1.x, a1.y, a1.z, a1.w};
            float br[8] = {b0.x, b0.y, b0.z, b0.w, b1.x, b1.y, b1.z, b1.w};
#pragma unroll
            for (int i = 0; i < 8; i++)
#pragma unroll
                for (int j = 0; j < 8; j++) acc[i][j] += ar[i] * br[j];
        }
        __syncthreads();
    }

#pragma unroll
    for (int i = 0; i < 8; i++) {
        const size_t row = (size_t)(m0 + trow * 8 + i);
#pragma unroll
        for (int jv = 0; jv < 2; jv++) {
            const int col = n0 + tcol * 8 + jv * 4;
            float4 o;
            o.x = acc[i][jv * 4 + 0];
            o.y = acc[i][jv * 4 + 1];
            o.z = acc[i][jv * 4 + 2];
            o.w = acc[i][jv * 4 + 3];
            if (bias) {
                o.x += bias[col + 0];
                o.y += bias[col + 1];
                o.z += bias[col + 2];
                o.w += bias[col + 3];
            }
            *(float4*)&C[row * N + col] = o;
        }
    }
}

// ----------------------------------------------------------------------------
// Flash attention (fp32, online softmax).
// Grid: (SEQ/64, HEADS, BATCH). 256 threads.
// Per block: 64 Q rows of one (b,h); loops over 2048 keys in chunks of 64.
// Thread (trow,tcol) owns S/P microtile rows trow*4+r, cols tcol*4+c
// and O microtile rows trow*4+r, d-cols tcol*4+c. Row-mates = contiguous
// 16-lane half-warp -> shuffle reductions for max/sum.
// smem: qs[d][i] (d-major), ks[d][j] (d-major, aliased by ps[j][i]), vs[j][d].
// ----------------------------------------------------------------------------
__global__ __launch_bounds__(256) void flash_attn(const float* __restrict__ qkv,
                                                  float* __restrict__ out)
{
    extern __shared__ float sm[];
    float* qs = sm;                    // [DH][LDP]
    float* ks = sm + DH * LDP;         // [DH][LDP]   (reused as ps after S phase)
    float* vs = sm + 2 * DH * LDP;     // [64][LDP]
    float* ps = ks;                    // [64 j][LDP i]

    const int tid  = threadIdx.x;
    const int trow = tid >> 4;         // 0..15  (i-group)
    const int tcol = tid & 15;         // 0..15  (j / d-group)
    const int h    = blockIdx.y;
    const int b    = blockIdx.z;
    const int q0   = blockIdx.x * 64;
    const size_t tb = (size_t)b * SEQ;

    const int lr = tid >> 4;           // loader row-part 0..15
    const int dg = (tid & 15) << 2;    // loader d     0..60

    // ---- load Q tile (scaled by 1/sqrt(64)) into qs[d][i] ----
#pragma unroll
    for (int it = 0; it < 4; it++) {
        const int i = lr + it * 16;
        float4 v = *(const float4*)(qkv + (tb + q0 + i) * QKVN + h * DH + dg);
        qs[(dg + 0) * LDP + i] = v.x * 0.125f;
        qs[(dg + 1) * LDP + i] = v.y * 0.125f;
        qs[(dg + 2) * LDP + i] = v.z * 0.125f;
        qs[(dg + 3) * LDP + i] = v.w * 0.125f;
    }

    float m[4], l[4], o[4][4];
#pragma unroll
    for (int r = 0; r < 4; r++) {
        m[r] = -1e30f;
        l[r] = 0.0f;
#pragma unroll
        for (int c = 0; c < 4; c++) o[r][c] = 0.0f;
    }

    for (int j0 = 0; j0 < SEQ; j0 += 64) {
        // ---- load K chunk (transposed) + V chunk ----
#pragma unroll
        for (int it = 0; it < 4; it++) {
            const int j = lr + it * 16;
            const float* base = qkv + (tb + j0 + j) * QKVN + h * DH + dg;
            float4 kv = *(const float4*)(base + DIMM);
            ks[(dg + 0) * LDP + j] = kv.x;
            ks[(dg + 1) * LDP + j] = kv.y;
            ks[(dg + 2) * LDP + j] = kv.z;
            ks[(dg + 3) * LDP + j] = kv.w;
            *(float4*)&vs[j * LDP + dg] = *(const float4*)(base + 2 * DIMM);
        }
        __syncthreads();

        // ---- S = (Q*scale) @ K^T, 4x4 microtile ----
        float s[4][4];
#pragma unroll
        for (int r = 0; r < 4; r++)
#pragma unroll
            for (int c = 0; c < 4; c++) s[r][c] = 0.0f;

#pragma unroll 8
        for (int d = 0; d < DH; d++) {
            float4 a  = *(const float4*)&qs[d * LDP + trow * 4];
            float4 bv = *(const float4*)&ks[d * LDP + tcol * 4];
            float ar[4] = {a.x, a.y, a.z, a.w};
            float br[4] = {bv.x, bv.y, bv.z, bv.w};
#pragma unroll
            for (int r = 0; r < 4; r++)
#pragma unroll
                for (int c = 0; c < 4; c++) s[r][c] += ar[r] * br[c];
        }

        // ---- online softmax (per row, reduced over 16 row-mate lanes) ----
#pragma unroll
        for (int r = 0; r < 4; r++) {
            float cm = fmaxf(fmaxf(s[r][0], s[r][1]), fmaxf(s[r][2], s[r][3]));
            cm = fmaxf(cm, __shfl_xor_sync(0xffffffffu, cm, 1));
            cm = fmaxf(cm, __shfl_xor_sync(0xffffffffu, cm, 2));
            cm = fmaxf(cm, __shfl_xor_sync(0xffffffffu, cm, 4));
            cm = fmaxf(cm, __shfl_xor_sync(0xffffffffu, cm, 8));
            const float mn = fmaxf(m[r], cm);
            const float al = __expf(m[r] - mn);
            float rs = 0.0f;
#pragma unroll
            for (int c = 0; c < 4; c++) {
                s[r][c] = __expf(s[r][c] - mn);
                rs += s[r][c];
            }
            rs += __shfl_xor_sync(0xffffffffu, rs, 1);
            rs += __shfl_xor_sync(0xffffffffu, rs, 2);
            rs += __shfl_xor_sync(0xffffffffu, rs, 4);
            rs += __shfl_xor_sync(0xffffffffu, rs, 8);
            l[r] = l[r] * al + rs;
            m[r] = mn;
#pragma unroll
            for (int c = 0; c < 4; c++) o[r][c] *= al;
        }

        __syncthreads();   // all ks reads done before ps (alias) is written
#pragma unroll
        for (int c = 0; c < 4; c++)
#pragma unroll
            for (int r = 0; r < 4; r++)
                ps[(tcol * 4 + c) * LDP + trow * 4 + r] = s[r][c];
        __syncthreads();

        // ---- O += P @ V ----
#pragma unroll 8
        for (int j = 0; j < 64; j++) {
            float4 a  = *(const float4*)&ps[j * LDP + trow * 4];
            float4 bv = *(const float4*)&vs[j * LDP + tcol * 4];
            float ar[4] = {a.x, a.y, a.z, a.w};
            float br[4] = {bv.x, bv.y, bv.z, bv.w};
#pragma unroll
            for (int r = 0; r < 4; r++)
#pragma unroll
                for (int c = 0; c < 4; c++) o[r][c] += ar[r] * br[c];
        }
        __syncthreads();   // before next chunk overwrites ks/ps/vs
    }

    // ---- epilogue: normalize and write to [token][h*64+d] ----
#pragma unroll
    for (int r = 0; r < 4; r++) {
        const float inv = 1.0f / l[r];
        float4 ov;
        ov.x = o[r][0] * inv;
        ov.y = o[r][1] * inv;
        ov.z = o[r][2] * inv;
        ov.w = o[r][3] * inv;
        *(float4*)&out[(tb + q0 + trow * 4 + r) * DIMM + h * DH + tcol * 4] = ov;
    }
}

// ----------------------------------------------------------------------------
// Launch
// ----------------------------------------------------------------------------
extern "C" void kernel_launch(void* const* d_in, const int* in_sizes, int n_in,
                              void* d_out, int out_size)
{
    const float* x    = (const float*)d_in[0];   // [4,2048,1024]
    const float* wqkv = (const float*)d_in[1];   // [1024,3072]
    const float* wout = (const float*)d_in[2];   // [1024,1024]
    const float* bout = (const float*)d_in[3];   // [1024]
    float* out = (float*)d_out;                  // [4,2048,1024]

    void *qkv_p, *attn_p;
    cudaGetSymbolAddress(&qkv_p, g_qkv);
    cudaGetSymbolAddress(&attn_p, g_attn);
    float* qkv  = (float*)qkv_p;
    float* attn = (float*)attn_p;

    const int SMEM = 3 * DH * LDP * (int)sizeof(float);  // 52224 B
    cudaFuncSetAttribute(flash_attn, cudaFuncAttributeMaxDynamicSharedMemorySize, SMEM);

    // 1) qkv = x @ w_qkv
    sgemm128<<<dim3(QKVN / 128, TOKENS / 128), 256>>>(x, wqkv, nullptr, qkv,
                                                      TOKENS, QKVN, DIMM);
    // 2) flash attention per (b, h), 64-row q tiles
    flash_attn<<<dim3(SEQ / 64, HEADS, BATCH), 256, SMEM>>>(qkv, attn);
    // 3) out = attn @ w_out + b_out
    sgemm128<<<dim3(DIMM / 128, TOKENS / 128), 256>>>(attn, wout, bout, out,
                                                      TOKENS, DIMM, DIMM);
}

// round 4
// speedup vs baseline: 1.2729x; 1.2729x over previous
#include <cuda_runtime.h>
#include <cuda_bf16.h>
#include <math.h>
#include <stdint.h>

// ---------------- problem constants ----------------
#define TOKENS 8192      // 4 * 2048
#define BATCH  4
#define SEQ    2048
#define DIMM   1024
#define QKVN   3072
#define HEADS  16
#define DH     64
#define LDP    68

// ---------------- scratch (__device__ globals; no cudaMalloc) ----------------
__device__ float         g_qkv [(size_t)TOKENS * QKVN];   // fp32 q|k|v
__device__ __nv_bfloat16 g_xhi [(size_t)TOKENS * DIMM];
__device__ __nv_bfloat16 g_xlo [(size_t)TOKENS * DIMM];
__device__ __nv_bfloat16 g_w1hi[(size_t)QKVN   * DIMM];   // w_qkv^T [3072][1024]
__device__ __nv_bfloat16 g_w1lo[(size_t)QKVN   * DIMM];
__device__ __nv_bfloat16 g_w2hi[(size_t)DIMM   * DIMM];   // w_out^T [1024][1024]
__device__ __nv_bfloat16 g_w2lo[(size_t)DIMM   * DIMM];
__device__ __nv_bfloat16 g_ahi [(size_t)TOKENS * DIMM];   // attn out
__device__ __nv_bfloat16 g_alo [(size_t)TOKENS * DIMM];

// ---------------- helpers ----------------
__device__ __forceinline__ uint32_t smem_u32(const void* p) {
    uint32_t a;
    asm("{ .reg .u64 t; cvta.to.shared.u64 t, %1; cvt.u32.u64 %0, t; }" : "=r"(a) : "l"(p));
    return a;
}
__device__ __forceinline__ void cpasync16(uint32_t dst, const void* src) {
    asm volatile("cp.async.cg.shared.global [%0], [%1], 16;" :: "r"(dst), "l"(src) : "memory");
}
__device__ __forceinline__ void mma16816(float* d, const uint32_t* a, const uint32_t* b) {
    asm volatile(
        "mma.sync.aligned.m16n8k16.row.col.f32.bf16.bf16.f32 "
        "{%0,%1,%2,%3}, {%4,%5,%6,%7}, {%8,%9}, {%0,%1,%2,%3};"
        : "+f"(d[0]), "+f"(d[1]), "+f"(d[2]), "+f"(d[3])
        : "r"(a[0]), "r"(a[1]), "r"(a[2]), "r"(a[3]), "r"(b[0]), "r"(b[1]));
}

// ---------------- GEMM over virtual K = 3*1024 -------------------------------
// C[M][N] = Ahi*Bhi^T + Ahi*Blo^T + Alo*Bhi^T (+bias). Chunks of BK=32:
//   region 0 (it  0..31): A=hi, B=hi
//   region 1 (it 32..63): A=hi, B=lo
//   region 2 (it 64..95): A=lo, B=hi
// bf16 mma.sync m16n8k16, fp32 accum. BM=BN=128, 256 thr (8 warps 2x4).
#define GLDS 40           // padded smem row stride (bf16)
#define GNIT 96           // 3 regions x 32 chunks

__global__ __launch_bounds__(256) void gemm_mma(
    const __nv_bfloat16* __restrict__ Ahi,
    const __nv_bfloat16* __restrict__ Alo,
    const __nv_bfloat16* __restrict__ Bhi,
    const __nv_bfloat16* __restrict__ Blo,
    const float* __restrict__ bias,
    float* __restrict__ C, int ldc)
{
    __shared__ __nv_bfloat16 As[2][128 * GLDS];
    __shared__ __nv_bfloat16 Bs[2][128 * GLDS];

    const int tid  = threadIdx.x;
    const int m0   = blockIdx.y * 128;
    const int n0   = blockIdx.x * 128;
    const int lane = tid & 31;
    const int w    = tid >> 5;
    const int wm   = (w >> 2) * 64;     // 0 or 64
    const int wn   = (w & 3) * 32;      // 0,32,64,96
    const int r    = lane >> 2;         // 0..7
    const int cq   = (lane & 3) * 2;    // 0,2,4,6

    const int row0 = tid >> 2;          // 0..63
    const int row1 = row0 + 64;         // 64..127
    const int seg  = (tid & 3) * 8;     // bf16 offset within 32-wide chunk

    float acc[4][4][4];
#pragma unroll
    for (int mt = 0; mt < 4; mt++)
#pragma unroll
        for (int nt = 0; nt < 4; nt++)
#pragma unroll
            for (int i = 0; i < 4; i++) acc[mt][nt][i] = 0.0f;

#define G_ISSUE(it, buf) do {                                                   \
    const int _rg = (it) >> 5;                                                  \
    const int _k0 = ((it) & 31) * 32;                                           \
    const __nv_bfloat16* _Asrc = (_rg < 2) ? Ahi : Alo;                         \
    const __nv_bfloat16* _Bsrc = (_rg == 1) ? Blo : Bhi;                        \
    cpasync16(smem_u32(&As[buf][row0 * GLDS + seg]),                            \
              _Asrc + (size_t)(m0 + row0) * DIMM + _k0 + seg);                  \
    cpasync16(smem_u32(&As[buf][row1 * GLDS + seg]),                            \
              _Asrc + (size_t)(m0 + row1) * DIMM + _k0 + seg);                  \
    cpasync16(smem_u32(&Bs[buf][row0 * GLDS + seg]),                            \
              _Bsrc + (size_t)(n0 + row0) * DIMM + _k0 + seg);                  \
    cpasync16(smem_u32(&Bs[buf][row1 * GLDS + seg]),                            \
              _Bsrc + (size_t)(n0 + row1) * DIMM + _k0 + seg);                  \
    asm volatile("cp.async.commit_group;" ::: "memory");                        \
} while (0)

    G_ISSUE(0, 0);

    for (int it = 0; it < GNIT; it++) {
        const int buf = it & 1;
        if (it + 1 < GNIT) {
            G_ISSUE(it + 1, buf ^ 1);
            asm volatile("cp.async.wait_group 1;" ::: "memory");
        } else {
            asm volatile("cp.async.wait_group 0;" ::: "memory");
        }
        __syncthreads();

#pragma unroll
        for (int ks = 0; ks < 2; ks++) {
            const int kk = ks * 16;
            uint32_t af[4][4], bfr[4][2];
#pragma unroll
            for (int mt = 0; mt < 4; mt++) {
                const __nv_bfloat16* ab = &As[buf][(wm + mt * 16) * GLDS + kk];
                af[mt][0] = *(const uint32_t*)&ab[(r    ) * GLDS + cq    ];
                af[mt][1] = *(const uint32_t*)&ab[(r + 8) * GLDS + cq    ];
                af[mt][2] = *(const uint32_t*)&ab[(r    ) * GLDS + cq + 8];
                af[mt][3] = *(const uint32_t*)&ab[(r + 8) * GLDS + cq + 8];
            }
#pragma unroll
            for (int nt = 0; nt < 4; nt++) {
                const __nv_bfloat16* bb = &Bs[buf][(wn + nt * 8) * GLDS + kk];
                bfr[nt][0] = *(const uint32_t*)&bb[r * GLDS + cq    ];
                bfr[nt][1] = *(const uint32_t*)&bb[r * GLDS + cq + 8];
            }
#pragma unroll
            for (int mt = 0; mt < 4; mt++)
#pragma unroll
                for (int nt = 0; nt < 4; nt++)
                    mma16816(acc[mt][nt], af[mt], bfr[nt]);
        }
        __syncthreads();
    }

    // epilogue
#pragma unroll
    for (int mt = 0; mt < 4; mt++) {
#pragma unroll
        for (int nt = 0; nt < 4; nt++) {
            const int row = m0 + wm + mt * 16 + r;
            const int col = n0 + wn + nt * 8 + cq;
            float bx = 0.0f, by = 0.0f;
            if (bias) { bx = bias[col]; by = bias[col + 1]; }
            float2 v0 = {acc[mt][nt][0] + bx, acc[mt][nt][1] + by};
            float2 v1 = {acc[mt][nt][2] + bx, acc[mt][nt][3] + by};
            *(float2*)&C[(size_t)row * ldc + col] = v0;
            *(float2*)&C[(size_t)(row + 8) * ldc + col] = v1;
        }
    }
}

// ---------------- converters ----------------
__global__ void split_kernel(const float4* __restrict__ in,
                             __nv_bfloat162* __restrict__ hi,
                             __nv_bfloat162* __restrict__ lo, int n4)
{
    const int i = blockIdx.x * blockDim.x + threadIdx.x;
    if (i >= n4) return;
    const float4 v = in[i];
    const __nv_bfloat16 hx = __float2bfloat16(v.x);
    const __nv_bfloat16 hy = __float2bfloat16(v.y);
    const __nv_bfloat16 hz = __float2bfloat16(v.z);
    const __nv_bfloat16 hw = __float2bfloat16(v.w);
    hi[2 * i + 0] = __nv_bfloat162(hx, hy);
    hi[2 * i + 1] = __nv_bfloat162(hz, hw);
    lo[2 * i + 0] = __nv_bfloat162(__float2bfloat16(v.x - __bfloat162float(hx)),
                                   __float2bfloat16(v.y - __bfloat162float(hy)));
    lo[2 * i + 1] = __nv_bfloat162(__float2bfloat16(v.z - __bfloat162float(hz)),
                                   __float2bfloat16(v.w - __bfloat162float(hw)));
}

// in[K][N] fp32 -> hi/lo [N][K] bf16 (transpose + split)
__global__ void tsplit_kernel(const float* __restrict__ in,
                              __nv_bfloat16* __restrict__ hi,
                              __nv_bfloat16* __restrict__ lo, int K, int N)
{
    __shared__ float t[32][33];
    const int n = blockIdx.x * 32 + threadIdx.x;
    const int k = blockIdx.y * 32 + threadIdx.y;
    t[threadIdx.y][threadIdx.x] = in[(size_t)k * N + n];
    __syncthreads();
    const int nn = blockIdx.x * 32 + threadIdx.y;
    const int kk = blockIdx.y * 32 + threadIdx.x;
    const float v = t[threadIdx.x][threadIdx.y];
    const __nv_bfloat16 h = __float2bfloat16(v);
    hi[(size_t)nn * K + kk] = h;
    lo[(size_t)nn * K + kk] = __float2bfloat16(v - __bfloat162float(h));
}

// ---------------- flash attention (fp32 SIMT) -------------------------------
__global__ __launch_bounds__(256) void flash_attn(const float* __restrict__ qkv)
{
    extern __shared__ float smf[];
    float* qs = smf;
    float* ks = smf + DH * LDP;
    float* vs = smf + 2 * DH * LDP;
    float* ps = ks;

    const int tid  = threadIdx.x;
    const int trow = tid >> 4;
    const int tcol = tid & 15;
    const int h    = blockIdx.y;
    const int b    = blockIdx.z;
    const int q0   = blockIdx.x * 64;
    const size_t tb = (size_t)b * SEQ;

    const int lr = tid >> 4;
    const int dg = (tid & 15) << 2;

#pragma unroll
    for (int it = 0; it < 4; it++) {
        const int i = lr + it * 16;
        float4 v = *(const float4*)(qkv + (tb + q0 + i) * QKVN + h * DH + dg);
        qs[(dg + 0) * LDP + i] = v.x * 0.125f;
        qs[(dg + 1) * LDP + i] = v.y * 0.125f;
        qs[(dg + 2) * LDP + i] = v.z * 0.125f;
        qs[(dg + 3) * LDP + i] = v.w * 0.125f;
    }

    float m[4], l[4], o[4][4];
#pragma unroll
    for (int r = 0; r < 4; r++) {
        m[r] = -1e30f; l[r] = 0.0f;
#pragma unroll
        for (int c = 0; c < 4; c++) o[r][c] = 0.0f;
    }

    for (int j0 = 0; j0 < SEQ; j0 += 64) {
#pragma unroll
        for (int it = 0; it < 4; it++) {
            const int j = lr + it * 16;
            const float* base = qkv + (tb + j0 + j) * QKVN + h * DH + dg;
            float4 kv = *(const float4*)(base + DIMM);
            ks[(dg + 0) * LDP + j] = kv.x;
            ks[(dg + 1) * LDP + j] = kv.y;
            ks[(dg + 2) * LDP + j] = kv.z;
            ks[(dg + 3) * LDP + j] = kv.w;
            *(float4*)&vs[j * LDP + dg] = *(const float4*)(base + 2 * DIMM);
        }
        __syncthreads();

        float s[4][4];
#pragma unroll
        for (int r = 0; r < 4; r++)
#pragma unroll
            for (int c = 0; c < 4; c++) s[r][c] = 0.0f;

#pragma unroll 8
        for (int d = 0; d < DH; d++) {
            float4 a  = *(const float4*)&qs[d * LDP + trow * 4];
            float4 bv = *(const float4*)&ks[d * LDP + tcol * 4];
            float ar[4] = {a.x, a.y, a.z, a.w};
            float br[4] = {bv.x, bv.y, bv.z, bv.w};
#pragma unroll
            for (int r = 0; r < 4; r++)
#pragma unroll
                for (int c = 0; c < 4; c++) s[r][c] += ar[r] * br[c];
        }

#pragma unroll
        for (int r = 0; r < 4; r++) {
            float cm = fmaxf(fmaxf(s[r][0], s[r][1]), fmaxf(s[r][2], s[r][3]));
            cm = fmaxf(cm, __shfl_xor_sync(0xffffffffu, cm, 1));
            cm = fmaxf(cm, __shfl_xor_sync(0xffffffffu, cm, 2));
            cm = fmaxf(cm, __shfl_xor_sync(0xffffffffu, cm, 4));
            cm = fmaxf(cm, __shfl_xor_sync(0xffffffffu, cm, 8));
            const float mn = fmaxf(m[r], cm);
            const float al = __expf(m[r] - mn);
            float rs = 0.0f;
#pragma unroll
            for (int c = 0; c < 4; c++) { s[r][c] = __expf(s[r][c] - mn); rs += s[r][c]; }
            rs += __shfl_xor_sync(0xffffffffu, rs, 1);
            rs += __shfl_xor_sync(0xffffffffu, rs, 2);
            rs += __shfl_xor_sync(0xffffffffu, rs, 4);
            rs += __shfl_xor_sync(0xffffffffu, rs, 8);
            l[r] = l[r] * al + rs;
            m[r] = mn;
#pragma unroll
            for (int c = 0; c < 4; c++) o[r][c] *= al;
        }

        __syncthreads();
#pragma unroll
        for (int c = 0; c < 4; c++)
#pragma unroll
            for (int r = 0; r < 4; r++)
                ps[(tcol * 4 + c) * LDP + trow * 4 + r] = s[r][c];
        __syncthreads();

#pragma unroll 8
        for (int j = 0; j < 64; j++) {
            float4 a  = *(const float4*)&ps[j * LDP + trow * 4];
            float4 bv = *(const float4*)&vs[j * LDP + tcol * 4];
            float ar[4] = {a.x, a.y, a.z, a.w};
            float br[4] = {bv.x, bv.y, bv.z, bv.w};
#pragma unroll
            for (int r = 0; r < 4; r++)
#pragma unroll
                for (int c = 0; c < 4; c++) o[r][c] += ar[r] * br[c];
        }
        __syncthreads();
    }

    // epilogue: write hi/lo bf16 split (feeds GEMM2's A operand)
#pragma unroll
    for (int r = 0; r < 4; r++) {
        const float inv = 1.0f / l[r];
        const size_t base = (tb + q0 + trow * 4 + r) * DIMM + h * DH + tcol * 4;
#pragma unroll
        for (int c = 0; c < 4; c++) {
            const float v = o[r][c] * inv;
            const __nv_bfloat16 hv = __float2bfloat16(v);
            g_ahi[base + c] = hv;
            g_alo[base + c] = __float2bfloat16(v - __bfloat162float(hv));
        }
    }
}

// ---------------- host ----------------
extern "C" void kernel_launch(void* const* d_in, const int* in_sizes, int n_in,
                              void* d_out, int out_size)
{
    const float* x    = (const float*)d_in[0];
    const float* wqkv = (const float*)d_in[1];
    const float* wout = (const float*)d_in[2];
    const float* bout = (const float*)d_in[3];
    float* out = (float*)d_out;

    void *qkv_p, *xhi_p, *xlo_p, *w1h_p, *w1l_p, *w2h_p, *w2l_p, *ahi_p, *alo_p;
    cudaGetSymbolAddress(&qkv_p, g_qkv);
    cudaGetSymbolAddress(&xhi_p, g_xhi);  cudaGetSymbolAddress(&xlo_p, g_xlo);
    cudaGetSymbolAddress(&w1h_p, g_w1hi); cudaGetSymbolAddress(&w1l_p, g_w1lo);
    cudaGetSymbolAddress(&w2h_p, g_w2hi); cudaGetSymbolAddress(&w2l_p, g_w2lo);
    cudaGetSymbolAddress(&ahi_p, g_ahi);  cudaGetSymbolAddress(&alo_p, g_alo);

    const int FSMEM = 3 * DH * LDP * (int)sizeof(float);
    cudaFuncSetAttribute(flash_attn, cudaFuncAttributeMaxDynamicSharedMemorySize, FSMEM);

    // 1) split x -> bf16 hi/lo
    {
        const int n4 = TOKENS * DIMM / 4;
        split_kernel<<<(n4 + 255) / 256, 256>>>((const float4*)x,
            (__nv_bfloat162*)xhi_p, (__nv_bfloat162*)xlo_p, n4);
    }
    // 2) transpose+split weights
    tsplit_kernel<<<dim3(QKVN / 32, DIMM / 32), dim3(32, 32)>>>(
        wqkv, (__nv_bfloat16*)w1h_p, (__nv_bfloat16*)w1l_p, DIMM, QKVN);
    tsplit_kernel<<<dim3(DIMM / 32, DIMM / 32), dim3(32, 32)>>>(
        wout, (__nv_bfloat16*)w2h_p, (__nv_bfloat16*)w2l_p, DIMM, DIMM);

    // 3) qkv = x @ w_qkv  (tensor cores, 3-term hi/lo)
    gemm_mma<<<dim3(QKVN / 128, TOKENS / 128), 256>>>(
        (const __nv_bfloat16*)xhi_p, (const __nv_bfloat16*)xlo_p,
        (const __nv_bfloat16*)w1h_p, (const __nv_bfloat16*)w1l_p,
        nullptr, (float*)qkv_p, QKVN);

    // 4) flash attention (fp32 SIMT; writes hi/lo bf16 attn output)
    flash_attn<<<dim3(SEQ / 64, HEADS, BATCH), 256, FSMEM>>>((const float*)qkv_p);

    // 5) out = attn @ w_out + b_out
    gemm_mma<<<dim3(DIMM / 128, TOKENS / 128), 256>>>(
        (const __nv_bfloat16*)ahi_p, (const __nv_bfloat16*)alo_p,
        (const __nv_bfloat16*)w2h_p, (const __nv_bfloat16*)w2l_p,
        bout, out, DIMM);
}

// round 5
// speedup vs baseline: 2.4386x; 1.9158x over previous
#include <cuda_runtime.h>
#include <cuda_bf16.h>
#include <math.h>
#include <stdint.h>

// ---------------- problem constants ----------------
#define TOKENS 8192      // 4 * 2048
#define BATCH  4
#define SEQ    2048
#define DIMM   1024
#define QKVN   3072
#define HEADS  16
#define DH     64

// ---------------- scratch (__device__ globals; no cudaMalloc) ----------------
__device__ __nv_bfloat16 g_xhi  [(size_t)TOKENS * DIMM];
__device__ __nv_bfloat16 g_xlo  [(size_t)TOKENS * DIMM];
__device__ __nv_bfloat16 g_w1hi [(size_t)QKVN   * DIMM];   // w_qkv^T [3072][1024]
__device__ __nv_bfloat16 g_w1lo [(size_t)QKVN   * DIMM];
__device__ __nv_bfloat16 g_w2hi [(size_t)DIMM   * DIMM];   // w_out^T [1024][1024]
__device__ __nv_bfloat16 g_w2lo [(size_t)DIMM   * DIMM];
__device__ __nv_bfloat16 g_qkvhi[(size_t)TOKENS * QKVN];   // q|k|v bf16 hi (q pre-scaled)
__device__ __nv_bfloat16 g_qkvlo[(size_t)TOKENS * QKVN];
__device__ __nv_bfloat16 g_vthi [(size_t)BATCH * HEADS * DH * SEQ]; // V^T [bh][d][j]
__device__ __nv_bfloat16 g_vtlo [(size_t)BATCH * HEADS * DH * SEQ];
__device__ __nv_bfloat16 g_ahi  [(size_t)TOKENS * DIMM];   // attn out hi
__device__ __nv_bfloat16 g_alo  [(size_t)TOKENS * DIMM];

// ---------------- helpers ----------------
__device__ __forceinline__ uint32_t smem_u32(const void* p) {
    uint32_t a;
    asm("{ .reg .u64 t; cvta.to.shared.u64 t, %1; cvt.u32.u64 %0, t; }" : "=r"(a) : "l"(p));
    return a;
}
__device__ __forceinline__ void cpasync16(uint32_t dst, const void* src) {
    asm volatile("cp.async.cg.shared.global [%0], [%1], 16;" :: "r"(dst), "l"(src) : "memory");
}
__device__ __forceinline__ void mma16816(float* d, const uint32_t* a, const uint32_t* b) {
    asm volatile(
        "mma.sync.aligned.m16n8k16.row.col.f32.bf16.bf16.f32 "
        "{%0,%1,%2,%3}, {%4,%5,%6,%7}, {%8,%9}, {%0,%1,%2,%3};"
        : "+f"(d[0]), "+f"(d[1]), "+f"(d[2]), "+f"(d[3])
        : "r"(a[0]), "r"(a[1]), "r"(a[2]), "r"(a[3]), "r"(b[0]), "r"(b[1]));
}
// split (a,b) fp32 into packed bf16x2 hi and lo words
__device__ __forceinline__ void pack2(float a, float b, uint32_t& hi, uint32_t& lo) {
    const __nv_bfloat16 ha = __float2bfloat16(a);
    const __nv_bfloat16 hb = __float2bfloat16(b);
    __nv_bfloat162 H(ha, hb);
    __nv_bfloat162 L(__float2bfloat16(a - __bfloat162float(ha)),
                     __float2bfloat16(b - __bfloat162float(hb)));
    hi = *(uint32_t*)&H;
    lo = *(uint32_t*)&L;
}

// ---------------- GEMM over virtual K = 3*1024 -------------------------------
// C = Ahi*Bhi^T + Ahi*Blo^T + Alo*Bhi^T. If Cf != null: fp32 out (+bias).
// Else: hi/lo bf16 split out to Chi/Clo, cols < qcols scaled by 0.125.
#define GLDS 40
#define GNIT 96

__global__ __launch_bounds__(256) void gemm_mma(
    const __nv_bfloat16* __restrict__ Ahi,
    const __nv_bfloat16* __restrict__ Alo,
    const __nv_bfloat16* __restrict__ Bhi,
    const __nv_bfloat16* __restrict__ Blo,
    const float* __restrict__ bias,
    float* __restrict__ Cf,
    __nv_bfloat16* __restrict__ Chi,
    __nv_bfloat16* __restrict__ Clo,
    int ldc, int qcols)
{
    __shared__ __nv_bfloat16 As[2][128 * GLDS];
    __shared__ __nv_bfloat16 Bs[2][128 * GLDS];

    const int tid  = threadIdx.x;
    const int m0   = blockIdx.y * 128;
    const int n0   = blockIdx.x * 128;
    const int lane = tid & 31;
    const int w    = tid >> 5;
    const int wm   = (w >> 2) * 64;
    const int wn   = (w & 3) * 32;
    const int r    = lane >> 2;
    const int cq   = (lane & 3) * 2;

    const int row0 = tid >> 2;
    const int row1 = row0 + 64;
    const int seg  = (tid & 3) * 8;

    float acc[4][4][4];
#pragma unroll
    for (int mt = 0; mt < 4; mt++)
#pragma unroll
        for (int nt = 0; nt < 4; nt++)
#pragma unroll
            for (int i = 0; i < 4; i++) acc[mt][nt][i] = 0.0f;

#define G_ISSUE(it, buf) do {                                                   \
    const int _rg = (it) >> 5;                                                  \
    const int _k0 = ((it) & 31) * 32;                                           \
    const __nv_bfloat16* _Asrc = (_rg < 2) ? Ahi : Alo;                         \
    const __nv_bfloat16* _Bsrc = (_rg == 1) ? Blo : Bhi;                        \
    cpasync16(smem_u32(&As[buf][row0 * GLDS + seg]),                            \
              _Asrc + (size_t)(m0 + row0) * DIMM + _k0 + seg);                  \
    cpasync16(smem_u32(&As[buf][row1 * GLDS + seg]),                            \
              _Asrc + (size_t)(m0 + row1) * DIMM + _k0 + seg);                  \
    cpasync16(smem_u32(&Bs[buf][row0 * GLDS + seg]),                            \
              _Bsrc + (size_t)(n0 + row0) * DIMM + _k0 + seg);                  \
    cpasync16(smem_u32(&Bs[buf][row1 * GLDS + seg]),                            \
              _Bsrc + (size_t)(n0 + row1) * DIMM + _k0 + seg);                  \
    asm volatile("cp.async.commit_group;" ::: "memory");                        \
} while (0)

    G_ISSUE(0, 0);

    for (int it = 0; it < GNIT; it++) {
        const int buf = it & 1;
        if (it + 1 < GNIT) {
            G_ISSUE(it + 1, buf ^ 1);
            asm volatile("cp.async.wait_group 1;" ::: "memory");
        } else {
            asm volatile("cp.async.wait_group 0;" ::: "memory");
        }
        __syncthreads();

#pragma unroll
        for (int ks = 0; ks < 2; ks++) {
            const int kk = ks * 16;
            uint32_t af[4][4], bfr[4][2];
#pragma unroll
            for (int mt = 0; mt < 4; mt++) {
                const __nv_bfloat16* ab = &As[buf][(wm + mt * 16) * GLDS + kk];
                af[mt][0] = *(const uint32_t*)&ab[(r    ) * GLDS + cq    ];
                af[mt][1] = *(const uint32_t*)&ab[(r + 8) * GLDS + cq    ];
                af[mt][2] = *(const uint32_t*)&ab[(r    ) * GLDS + cq + 8];
                af[mt][3] = *(const uint32_t*)&ab[(r + 8) * GLDS + cq + 8];
            }
#pragma unroll
            for (int nt = 0; nt < 4; nt++) {
                const __nv_bfloat16* bb = &Bs[buf][(wn + nt * 8) * GLDS + kk];
                bfr[nt][0] = *(const uint32_t*)&bb[r * GLDS + cq    ];
                bfr[nt][1] = *(const uint32_t*)&bb[r * GLDS + cq + 8];
            }
#pragma unroll
            for (int mt = 0; mt < 4; mt++)
#pragma unroll
                for (int nt = 0; nt < 4; nt++)
                    mma16816(acc[mt][nt], af[mt], bfr[nt]);
        }
        __syncthreads();
    }

#pragma unroll
    for (int mt = 0; mt < 4; mt++) {
#pragma unroll
        for (int nt = 0; nt < 4; nt++) {
            const int row = m0 + wm + mt * 16 + r;
            const int col = n0 + wn + nt * 8 + cq;
            float v0 = acc[mt][nt][0], v1 = acc[mt][nt][1];
            float v2 = acc[mt][nt][2], v3 = acc[mt][nt][3];
            if (Cf) {
                float bx = 0.0f, by = 0.0f;
                if (bias) { bx = bias[col]; by = bias[col + 1]; }
                float2 o0 = {v0 + bx, v1 + by};
                float2 o1 = {v2 + bx, v3 + by};
                *(float2*)&Cf[(size_t)row * ldc + col] = o0;
                *(float2*)&Cf[(size_t)(row + 8) * ldc + col] = o1;
            } else {
                if (col < qcols) { v0 *= 0.125f; v1 *= 0.125f; v2 *= 0.125f; v3 *= 0.125f; }
                uint32_t H, L;
                pack2(v0, v1, H, L);
                *(uint32_t*)&Chi[(size_t)row * ldc + col] = H;
                *(uint32_t*)&Clo[(size_t)row * ldc + col] = L;
                pack2(v2, v3, H, L);
                *(uint32_t*)&Chi[(size_t)(row + 8) * ldc + col] = H;
                *(uint32_t*)&Clo[(size_t)(row + 8) * ldc + col] = L;
            }
        }
    }
}

// ---------------- converters ----------------
__global__ void split_kernel(const float4* __restrict__ in,
                             __nv_bfloat162* __restrict__ hi,
                             __nv_bfloat162* __restrict__ lo, int n4)
{
    const int i = blockIdx.x * blockDim.x + threadIdx.x;
    if (i >= n4) return;
    const float4 v = in[i];
    uint32_t h0, l0, h1, l1;
    pack2(v.x, v.y, h0, l0);
    pack2(v.z, v.w, h1, l1);
    ((uint32_t*)hi)[2 * i + 0] = h0;
    ((uint32_t*)hi)[2 * i + 1] = h1;
    ((uint32_t*)lo)[2 * i + 0] = l0;
    ((uint32_t*)lo)[2 * i + 1] = l1;
}

__global__ void tsplit_kernel(const float* __restrict__ in,
                              __nv_bfloat16* __restrict__ hi,
                              __nv_bfloat16* __restrict__ lo, int K, int N)
{
    __shared__ float t[32][33];
    const int n = blockIdx.x * 32 + threadIdx.x;
    const int k = blockIdx.y * 32 + threadIdx.y;
    t[threadIdx.y][threadIdx.x] = in[(size_t)k * N + n];
    __syncthreads();
    const int nn = blockIdx.x * 32 + threadIdx.y;
    const int kk = blockIdx.y * 32 + threadIdx.x;
    const float v = t[threadIdx.x][threadIdx.y];
    const __nv_bfloat16 h = __float2bfloat16(v);
    hi[(size_t)nn * K + kk] = h;
    lo[(size_t)nn * K + kk] = __float2bfloat16(v - __bfloat162float(h));
}

// V transpose: qkv[token][2048 + h*64 + d] -> vt[(b*16+h)*64 + d][j]
__global__ void vtrans_kernel(const __nv_bfloat16* __restrict__ qkv,
                              __nv_bfloat16* __restrict__ vt)
{
    __shared__ __nv_bfloat16 t[32][33];
    const int bh = blockIdx.z;
    const int b  = bh >> 4;
    const int h  = bh & 15;
    const int j0 = blockIdx.x * 32;
    const int d0 = blockIdx.y * 32;
    t[threadIdx.y][threadIdx.x] =
        qkv[(size_t)(b * SEQ + j0 + threadIdx.y) * QKVN + 2048 + h * DH + d0 + threadIdx.x];
    __syncthreads();
    vt[((size_t)bh * DH + d0 + threadIdx.y) * SEQ + j0 + threadIdx.x] = t[threadIdx.x][threadIdx.y];
}

// ---------------- flash attention on tensor cores ----------------------------
// Block: 128 q rows of one (b,h); 256 threads = 8 warps x 16 q rows.
// Iterates 128-key chunks; K/V double-buffered via cp.async.
#define LDK 72
#define LDV 136
#define KSTG (128 * LDK)
#define VSTG (DH * LDV)
#define STG_ELEMS (2 * KSTG + 2 * VSTG)          // 35840 bf16
#define ASMEM (2 * STG_ELEMS * 2)                // 143360 B
#define NITER (SEQ / 128)

__global__ __launch_bounds__(256, 1) void flash_mma(
    const __nv_bfloat16* __restrict__ qkvhi,
    const __nv_bfloat16* __restrict__ qkvlo,
    const __nv_bfloat16* __restrict__ vthi,
    const __nv_bfloat16* __restrict__ vtlo,
    __nv_bfloat16* __restrict__ ahi,
    __nv_bfloat16* __restrict__ alo)
{
    extern __shared__ __nv_bfloat16 smb[];

    const int tid  = threadIdx.x;
    const int lane = tid & 31;
    const int w    = tid >> 5;
    const int r    = lane >> 2;
    const int cq   = (lane & 3) * 2;
    const int h    = blockIdx.y;
    const int b    = blockIdx.z;
    const int q0   = blockIdx.x * 128;
    const size_t tb = (size_t)b * SEQ;
    const int bh   = b * HEADS + h;

#define A_ISSUE(it, st) do {                                                     \
    const int _j0 = (it) * 128;                                                  \
    __nv_bfloat16* _khi = smb + (st) * STG_ELEMS;                                \
    __nv_bfloat16* _klo = _khi + KSTG;                                           \
    __nv_bfloat16* _vhi = _klo + KSTG;                                           \
    __nv_bfloat16* _vlo = _vhi + VSTG;                                           \
    for (int sg = tid; sg < 1024; sg += 256) {                                   \
        const int _j = sg >> 3, _so = (sg & 7) * 8;                              \
        const size_t _src = (tb + _j0 + _j) * QKVN + DIMM + h * DH + _so;        \
        cpasync16(smem_u32(_khi + _j * LDK + _so), qkvhi + _src);                \
        cpasync16(smem_u32(_klo + _j * LDK + _so), qkvlo + _src);                \
    }                                                                            \
    for (int sg = tid; sg < 1024; sg += 256) {                                   \
        const int _d = sg >> 4, _so = (sg & 15) * 8;                             \
        const size_t _src = ((size_t)bh * DH + _d) * SEQ + _j0 + _so;            \
        cpasync16(smem_u32(_vhi + _d * LDV + _so), vthi + _src);                 \
        cpasync16(smem_u32(_vlo + _d * LDV + _so), vtlo + _src);                 \
    }                                                                            \
    asm volatile("cp.async.commit_group;" ::: "memory");                         \
} while (0)

    // ---- Q fragments (loaded once, q already scaled by 0.125) ----
    uint32_t qh[4][4], ql[4][4];
    {
        const __nv_bfloat16* qbh = qkvhi + (tb + q0 + w * 16) * QKVN + h * DH;
        const __nv_bfloat16* qbl = qkvlo + (tb + q0 + w * 16) * QKVN + h * DH;
#pragma unroll
        for (int g = 0; g < 4; g++) {
            qh[g][0] = *(const uint32_t*)(qbh + (size_t)r * QKVN + g * 16 + cq);
            qh[g][1] = *(const uint32_t*)(qbh + (size_t)(r + 8) * QKVN + g * 16 + cq);
            qh[g][2] = *(const uint32_t*)(qbh + (size_t)r * QKVN + g * 16 + cq + 8);
            qh[g][3] = *(const uint32_t*)(qbh + (size_t)(r + 8) * QKVN + g * 16 + cq + 8);
            ql[g][0] = *(const uint32_t*)(qbl + (size_t)r * QKVN + g * 16 + cq);
            ql[g][1] = *(const uint32_t*)(qbl + (size_t)(r + 8) * QKVN + g * 16 + cq);
            ql[g][2] = *(const uint32_t*)(qbl + (size_t)r * QKVN + g * 16 + cq + 8);
            ql[g][3] = *(const uint32_t*)(qbl + (size_t)(r + 8) * QKVN + g * 16 + cq + 8);
        }
    }

    float m0 = -1e30f, m1 = -1e30f, l0 = 0.0f, l1 = 0.0f;
    float o[8][4];
#pragma unroll
    for (int nt = 0; nt < 8; nt++)
#pragma unroll
        for (int i = 0; i < 4; i++) o[nt][i] = 0.0f;

    A_ISSUE(0, 0);

    for (int it = 0; it < NITER; it++) {
        const int st = it & 1;
        if (it + 1 < NITER) {
            A_ISSUE(it + 1, st ^ 1);
            asm volatile("cp.async.wait_group 1;" ::: "memory");
        } else {
            asm volatile("cp.async.wait_group 0;" ::: "memory");
        }
        __syncthreads();

        const __nv_bfloat16* khi = smb + st * STG_ELEMS;
        const __nv_bfloat16* klo = khi + KSTG;
        const __nv_bfloat16* vhi = klo + KSTG;
        const __nv_bfloat16* vlo = vhi + VSTG;

        // ---- S = Q K^T (3-term hi/lo) ----
        float s[16][4];
#pragma unroll
        for (int nt = 0; nt < 16; nt++)
#pragma unroll
            for (int i = 0; i < 4; i++) s[nt][i] = 0.0f;

#pragma unroll
        for (int nt = 0; nt < 16; nt++) {
            const __nv_bfloat16* kbh = khi + (nt * 8 + r) * LDK;
            const __nv_bfloat16* kbl = klo + (nt * 8 + r) * LDK;
            uint32_t kh_[4][2], kl_[4][2];
#pragma unroll
            for (int g = 0; g < 4; g++) {
                kh_[g][0] = *(const uint32_t*)(kbh + g * 16 + cq);
                kh_[g][1] = *(const uint32_t*)(kbh + g * 16 + cq + 8);
                kl_[g][0] = *(const uint32_t*)(kbl + g * 16 + cq);
                kl_[g][1] = *(const uint32_t*)(kbl + g * 16 + cq + 8);
            }
#pragma unroll
            for (int g = 0; g < 4; g++) {
                mma16816(s[nt], qh[g], kh_[g]);
                mma16816(s[nt], ql[g], kh_[g]);
                mma16816(s[nt], qh[g], kl_[g]);
            }
        }

        // ---- online softmax (rows r and r+8) ----
        float mx0 = -1e30f, mx1 = -1e30f;
#pragma unroll
        for (int nt = 0; nt < 16; nt++) {
            mx0 = fmaxf(mx0, fmaxf(s[nt][0], s[nt][1]));
            mx1 = fmaxf(mx1, fmaxf(s[nt][2], s[nt][3]));
        }
        mx0 = fmaxf(mx0, __shfl_xor_sync(0xffffffffu, mx0, 1));
        mx0 = fmaxf(mx0, __shfl_xor_sync(0xffffffffu, mx0, 2));
        mx1 = fmaxf(mx1, __shfl_xor_sync(0xffffffffu, mx1, 1));
        mx1 = fmaxf(mx1, __shfl_xor_sync(0xffffffffu, mx1, 2));
        const float mn0 = fmaxf(m0, mx0);
        const float mn1 = fmaxf(m1, mx1);
        const float al0 = __expf(m0 - mn0);
        const float al1 = __expf(m1 - mn1);
        m0 = mn0; m1 = mn1;
        float rs0 = 0.0f, rs1 = 0.0f;
#pragma unroll
        for (int nt = 0; nt < 16; nt++) {
            s[nt][0] = __expf(s[nt][0] - mn0);
            s[nt][1] = __expf(s[nt][1] - mn0);
            s[nt][2] = __expf(s[nt][2] - mn1);
            s[nt][3] = __expf(s[nt][3] - mn1);
            rs0 += s[nt][0] + s[nt][1];
            rs1 += s[nt][2] + s[nt][3];
        }
        rs0 += __shfl_xor_sync(0xffffffffu, rs0, 1);
        rs0 += __shfl_xor_sync(0xffffffffu, rs0, 2);
        rs1 += __shfl_xor_sync(0xffffffffu, rs1, 1);
        rs1 += __shfl_xor_sync(0xffffffffu, rs1, 2);
        l0 = l0 * al0 + rs0;
        l1 = l1 * al1 + rs1;
#pragma unroll
        for (int nt = 0; nt < 8; nt++) {
            o[nt][0] *= al0; o[nt][1] *= al0;
            o[nt][2] *= al1; o[nt][3] *= al1;
        }

        // ---- pack P (hi/lo) as A-fragments ----
        uint32_t ph[8][4], pl[8][4];
#pragma unroll
        for (int jg = 0; jg < 8; jg++) {
            pack2(s[2 * jg    ][0], s[2 * jg    ][1], ph[jg][0], pl[jg][0]);
            pack2(s[2 * jg    ][2], s[2 * jg    ][3], ph[jg][1], pl[jg][1]);
            pack2(s[2 * jg + 1][0], s[2 * jg + 1][1], ph[jg][2], pl[jg][2]);
            pack2(s[2 * jg + 1][2], s[2 * jg + 1][3], ph[jg][3], pl[jg][3]);
        }

        // ---- O += P V (3-term hi/lo), V is [d][j] ----
#pragma unroll
        for (int nt = 0; nt < 8; nt++) {
            const __nv_bfloat16* vbh = vhi + (nt * 8 + r) * LDV;
            const __nv_bfloat16* vbl = vlo + (nt * 8 + r) * LDV;
#pragma unroll
            for (int jg = 0; jg < 8; jg++) {
                uint32_t vh_[2], vl_[2];
                vh_[0] = *(const uint32_t*)(vbh + jg * 16 + cq);
                vh_[1] = *(const uint32_t*)(vbh + jg * 16 + cq + 8);
                vl_[0] = *(const uint32_t*)(vbl + jg * 16 + cq);
                vl_[1] = *(const uint32_t*)(vbl + jg * 16 + cq + 8);
                mma16816(o[nt], ph[jg], vh_);
                mma16816(o[nt], pl[jg], vh_);
                mma16816(o[nt], ph[jg], vl_);
            }
        }
        __syncthreads();
    }

    // ---- epilogue: O/l, write hi/lo bf16 for GEMM2 ----
    const float inv0 = 1.0f / l0;
    const float inv1 = 1.0f / l1;
#pragma unroll
    for (int nt = 0; nt < 8; nt++) {
        const size_t b0 = (tb + q0 + w * 16 + r) * DIMM + h * DH + nt * 8 + cq;
        const size_t b1 = (tb + q0 + w * 16 + r + 8) * DIMM + h * DH + nt * 8 + cq;
        uint32_t H, L;
        pack2(o[nt][0] * inv0, o[nt][1] * inv0, H, L);
        *(uint32_t*)(ahi + b0) = H;
        *(uint32_t*)(alo + b0) = L;
        pack2(o[nt][2] * inv1, o[nt][3] * inv1, H, L);
        *(uint32_t*)(ahi + b1) = H;
        *(uint32_t*)(alo + b1) = L;
    }
}

// ---------------- host ----------------
extern "C" void kernel_launch(void* const* d_in, const int* in_sizes, int n_in,
                              void* d_out, int out_size)
{
    const float* x    = (const float*)d_in[0];
    const float* wqkv = (const float*)d_in[1];
    const float* wout = (const float*)d_in[2];
    const float* bout = (const float*)d_in[3];
    float* out = (float*)d_out;

    void *xhi_p, *xlo_p, *w1h_p, *w1l_p, *w2h_p, *w2l_p;
    void *qh_p, *ql_p, *vth_p, *vtl_p, *ahi_p, *alo_p;
    cudaGetSymbolAddress(&xhi_p, g_xhi);   cudaGetSymbolAddress(&xlo_p, g_xlo);
    cudaGetSymbolAddress(&w1h_p, g_w1hi);  cudaGetSymbolAddress(&w1l_p, g_w1lo);
    cudaGetSymbolAddress(&w2h_p, g_w2hi);  cudaGetSymbolAddress(&w2l_p, g_w2lo);
    cudaGetSymbolAddress(&qh_p,  g_qkvhi); cudaGetSymbolAddress(&ql_p,  g_qkvlo);
    cudaGetSymbolAddress(&vth_p, g_vthi);  cudaGetSymbolAddress(&vtl_p, g_vtlo);
    cudaGetSymbolAddress(&ahi_p, g_ahi);   cudaGetSymbolAddress(&alo_p, g_alo);

    cudaFuncSetAttribute(flash_mma, cudaFuncAttributeMaxDynamicSharedMemorySize, ASMEM);

    // 1) split x -> bf16 hi/lo
    {
        const int n4 = TOKENS * DIMM / 4;
        split_kernel<<<(n4 + 255) / 256, 256>>>((const float4*)x,
            (__nv_bfloat162*)xhi_p, (__nv_bfloat162*)xlo_p, n4);
    }
    // 2) transpose+split weights
    tsplit_kernel<<<dim3(QKVN / 32, DIMM / 32), dim3(32, 32)>>>(
        wqkv, (__nv_bfloat16*)w1h_p, (__nv_bfloat16*)w1l_p, DIMM, QKVN);
    tsplit_kernel<<<dim3(DIMM / 32, DIMM / 32), dim3(32, 32)>>>(
        wout, (__nv_bfloat16*)w2h_p, (__nv_bfloat16*)w2l_p, DIMM, DIMM);

    // 3) qkv = x @ w_qkv -> hi/lo bf16, q pre-scaled by 0.125
    gemm_mma<<<dim3(QKVN / 128, TOKENS / 128), 256>>>(
        (const __nv_bfloat16*)xhi_p, (const __nv_bfloat16*)xlo_p,
        (const __nv_bfloat16*)w1h_p, (const __nv_bfloat16*)w1l_p,
        nullptr, nullptr,
        (__nv_bfloat16*)qh_p, (__nv_bfloat16*)ql_p, QKVN, DIMM);

    // 4) transpose V -> [bh][d][j]
    vtrans_kernel<<<dim3(SEQ / 32, DH / 32, BATCH * HEADS), dim3(32, 32)>>>(
        (const __nv_bfloat16*)qh_p, (__nv_bfloat16*)vth_p);
    vtrans_kernel<<<dim3(SEQ / 32, DH / 32, BATCH * HEADS), dim3(32, 32)>>>(
        (const __nv_bfloat16*)ql_p, (__nv_bfloat16*)vtl_p);

    // 5) flash attention on tensor cores
    flash_mma<<<dim3(SEQ / 128, HEADS, BATCH), 256, ASMEM>>>(
        (const __nv_bfloat16*)qh_p, (const __nv_bfloat16*)ql_p,
        (const __nv_bfloat16*)vth_p, (const __nv_bfloat16*)vtl_p,
        (__nv_bfloat16*)ahi_p, (__nv_bfloat16*)alo_p);

    // 6) out = attn @ w_out + b_out (fp32)
    gemm_mma<<<dim3(DIMM / 128, TOKENS / 128), 256>>>(
        (const __nv_bfloat16*)ahi_p, (const __nv_bfloat16*)alo_p,
        (const __nv_bfloat16*)w2h_p, (const __nv_bfloat16*)w2l_p,
        bout, out, nullptr, nullptr, DIMM, 0);
}

// round 6
// speedup vs baseline: 2.4795x; 1.0168x over previous
#include <cuda_runtime.h>
#include <cuda_bf16.h>
#include <math.h>
#include <stdint.h>

// ---------------- problem constants ----------------
#define TOKENS 8192      // 4 * 2048
#define BATCH  4
#define SEQ    2048
#define DIMM   1024
#define QKVN   3072
#define HEADS  16
#define DH     64

// ---------------- scratch (__device__ globals; no cudaMalloc) ----------------
__device__ __nv_bfloat16 g_xhi  [(size_t)TOKENS * DIMM];
__device__ __nv_bfloat16 g_xlo  [(size_t)TOKENS * DIMM];
__device__ __nv_bfloat16 g_w1hi [(size_t)QKVN   * DIMM];
__device__ __nv_bfloat16 g_w1lo [(size_t)QKVN   * DIMM];
__device__ __nv_bfloat16 g_w2hi [(size_t)DIMM   * DIMM];
__device__ __nv_bfloat16 g_w2lo [(size_t)DIMM   * DIMM];
__device__ __nv_bfloat16 g_qkvhi[(size_t)TOKENS * QKVN];   // q|k|v (q pre-scaled)
__device__ __nv_bfloat16 g_qkvlo[(size_t)TOKENS * QKVN];
__device__ __nv_bfloat16 g_vthi [(size_t)BATCH * HEADS * DH * SEQ]; // V^T [bh][d][j]
__device__ __nv_bfloat16 g_vtlo [(size_t)BATCH * HEADS * DH * SEQ];
__device__ __nv_bfloat16 g_ahi  [(size_t)TOKENS * DIMM];
__device__ __nv_bfloat16 g_alo  [(size_t)TOKENS * DIMM];

// ---------------- helpers ----------------
__device__ __forceinline__ uint32_t smem_u32(const void* p) {
    uint32_t a;
    asm("{ .reg .u64 t; cvta.to.shared.u64 t, %1; cvt.u32.u64 %0, t; }" : "=r"(a) : "l"(p));
    return a;
}
__device__ __forceinline__ void cpasync16(uint32_t dst, const void* src) {
    asm volatile("cp.async.cg.shared.global [%0], [%1], 16;" :: "r"(dst), "l"(src) : "memory");
}
__device__ __forceinline__ void mma16816(float* d, const uint32_t* a, const uint32_t* b) {
    asm volatile(
        "mma.sync.aligned.m16n8k16.row.col.f32.bf16.bf16.f32 "
        "{%0,%1,%2,%3}, {%4,%5,%6,%7}, {%8,%9}, {%0,%1,%2,%3};"
        : "+f"(d[0]), "+f"(d[1]), "+f"(d[2]), "+f"(d[3])
        : "r"(a[0]), "r"(a[1]), "r"(a[2]), "r"(a[3]), "r"(b[0]), "r"(b[1]));
}
__device__ __forceinline__ void ldsm4(uint32_t* d, uint32_t addr) {
    asm volatile("ldmatrix.sync.aligned.m8n8.x4.shared.b16 {%0,%1,%2,%3}, [%4];"
        : "=r"(d[0]), "=r"(d[1]), "=r"(d[2]), "=r"(d[3]) : "r"(addr));
}
__device__ __forceinline__ void pack2(float a, float b, uint32_t& hi, uint32_t& lo) {
    const __nv_bfloat16 ha = __float2bfloat16(a);
    const __nv_bfloat16 hb = __float2bfloat16(b);
    __nv_bfloat162 H(ha, hb);
    __nv_bfloat162 L(__float2bfloat16(a - __bfloat162float(ha)),
                     __float2bfloat16(b - __bfloat162float(hb)));
    hi = *(uint32_t*)&H;
    lo = *(uint32_t*)&L;
}

// ---------------- GEMM over virtual K = 3*1024 -------------------------------
#define GLDS 40
#define GNIT 96

__global__ __launch_bounds__(256) void gemm_mma(
    const __nv_bfloat16* __restrict__ Ahi,
    const __nv_bfloat16* __restrict__ Alo,
    const __nv_bfloat16* __restrict__ Bhi,
    const __nv_bfloat16* __restrict__ Blo,
    const float* __restrict__ bias,
    float* __restrict__ Cf,
    __nv_bfloat16* __restrict__ Chi,
    __nv_bfloat16* __restrict__ Clo,
    int ldc, int qcols)
{
    __shared__ __nv_bfloat16 As[2][128 * GLDS];
    __shared__ __nv_bfloat16 Bs[2][128 * GLDS];

    const int tid  = threadIdx.x;
    const int m0   = blockIdx.y * 128;
    const int n0   = blockIdx.x * 128;
    const int lane = tid & 31;
    const int w    = tid >> 5;
    const int wm   = (w >> 2) * 64;
    const int wn   = (w & 3) * 32;
    const int r    = lane >> 2;
    const int cq   = (lane & 3) * 2;

    const int row0 = tid >> 2;
    const int row1 = row0 + 64;
    const int seg  = (tid & 3) * 8;

    // ldmatrix lane-derived offsets
    const int a_row  = (lane & 7) + ((lane >> 3) & 1) * 8;
    const int a_koff = ((lane >> 4) & 1) * 8;
    const int b_row  = ((lane >> 4) & 1) * 8 + (lane & 7);
    const int b_koff = ((lane >> 3) & 1) * 8;

    float acc[4][4][4];
#pragma unroll
    for (int mt = 0; mt < 4; mt++)
#pragma unroll
        for (int nt = 0; nt < 4; nt++)
#pragma unroll
            for (int i = 0; i < 4; i++) acc[mt][nt][i] = 0.0f;

#define G_ISSUE(it, buf) do {                                                   \
    const int _rg = (it) >> 5;                                                  \
    const int _k0 = ((it) & 31) * 32;                                           \
    const __nv_bfloat16* _Asrc = (_rg < 2) ? Ahi : Alo;                         \
    const __nv_bfloat16* _Bsrc = (_rg == 1) ? Blo : Bhi;                        \
    cpasync16(smem_u32(&As[buf][row0 * GLDS + seg]),                            \
              _Asrc + (size_t)(m0 + row0) * DIMM + _k0 + seg);                  \
    cpasync16(smem_u32(&As[buf][row1 * GLDS + seg]),                            \
              _Asrc + (size_t)(m0 + row1) * DIMM + _k0 + seg);                  \
    cpasync16(smem_u32(&Bs[buf][row0 * GLDS + seg]),                            \
              _Bsrc + (size_t)(n0 + row0) * DIMM + _k0 + seg);                  \
    cpasync16(smem_u32(&Bs[buf][row1 * GLDS + seg]),                            \
              _Bsrc + (size_t)(n0 + row1) * DIMM + _k0 + seg);                  \
    asm volatile("cp.async.commit_group;" ::: "memory");                        \
} while (0)

    G_ISSUE(0, 0);

    for (int it = 0; it < GNIT; it++) {
        const int buf = it & 1;
        if (it + 1 < GNIT) {
            G_ISSUE(it + 1, buf ^ 1);
            asm volatile("cp.async.wait_group 1;" ::: "memory");
        } else {
            asm volatile("cp.async.wait_group 0;" ::: "memory");
        }
        __syncthreads();

        const uint32_t asb = smem_u32(&As[buf][0]);
        const uint32_t bsb = smem_u32(&Bs[buf][0]);

#pragma unroll
        for (int ks = 0; ks < 2; ks++) {
            const int kk = ks * 16;
            uint32_t af[4][4], bfr[2][4];
#pragma unroll
            for (int mt = 0; mt < 4; mt++)
                ldsm4(af[mt], asb + ((wm + mt * 16 + a_row) * GLDS + kk + a_koff) * 2);
#pragma unroll
            for (int p = 0; p < 2; p++)
                ldsm4(bfr[p], bsb + ((wn + p * 16 + b_row) * GLDS + kk + b_koff) * 2);
#pragma unroll
            for (int mt = 0; mt < 4; mt++)
#pragma unroll
                for (int nt = 0; nt < 4; nt++)
                    mma16816(acc[mt][nt], af[mt], &bfr[nt >> 1][(nt & 1) * 2]);
        }
        __syncthreads();
    }

#pragma unroll
    for (int mt = 0; mt < 4; mt++) {
#pragma unroll
        for (int nt = 0; nt < 4; nt++) {
            const int row = m0 + wm + mt * 16 + r;
            const int col = n0 + wn + nt * 8 + cq;
            float v0 = acc[mt][nt][0], v1 = acc[mt][nt][1];
            float v2 = acc[mt][nt][2], v3 = acc[mt][nt][3];
            if (Cf) {
                float bx = 0.0f, by = 0.0f;
                if (bias) { bx = bias[col]; by = bias[col + 1]; }
                float2 o0 = {v0 + bx, v1 + by};
                float2 o1 = {v2 + bx, v3 + by};
                *(float2*)&Cf[(size_t)row * ldc + col] = o0;
                *(float2*)&Cf[(size_t)(row + 8) * ldc + col] = o1;
            } else {
                if (col < qcols) { v0 *= 0.125f; v1 *= 0.125f; v2 *= 0.125f; v3 *= 0.125f; }
                uint32_t H, L;
                pack2(v0, v1, H, L);
                *(uint32_t*)&Chi[(size_t)row * ldc + col] = H;
                *(uint32_t*)&Clo[(size_t)row * ldc + col] = L;
                pack2(v2, v3, H, L);
                *(uint32_t*)&Chi[(size_t)(row + 8) * ldc + col] = H;
                *(uint32_t*)&Clo[(size_t)(row + 8) * ldc + col] = L;
            }
        }
    }
}

// ---------------- converters ----------------
__global__ void split_kernel(const float4* __restrict__ in,
                             __nv_bfloat162* __restrict__ hi,
                             __nv_bfloat162* __restrict__ lo, int n4)
{
    const int i = blockIdx.x * blockDim.x + threadIdx.x;
    if (i >= n4) return;
    const float4 v = in[i];
    uint32_t h0, l0, h1, l1;
    pack2(v.x, v.y, h0, l0);
    pack2(v.z, v.w, h1, l1);
    ((uint32_t*)hi)[2 * i + 0] = h0;
    ((uint32_t*)hi)[2 * i + 1] = h1;
    ((uint32_t*)lo)[2 * i + 0] = l0;
    ((uint32_t*)lo)[2 * i + 1] = l1;
}

__global__ void tsplit_kernel(const float* __restrict__ in,
                              __nv_bfloat16* __restrict__ hi,
                              __nv_bfloat16* __restrict__ lo, int K, int N)
{
    __shared__ float t[32][33];
    const int n = blockIdx.x * 32 + threadIdx.x;
    const int k = blockIdx.y * 32 + threadIdx.y;
    t[threadIdx.y][threadIdx.x] = in[(size_t)k * N + n];
    __syncthreads();
    const int nn = blockIdx.x * 32 + threadIdx.y;
    const int kk = blockIdx.y * 32 + threadIdx.x;
    const float v = t[threadIdx.x][threadIdx.y];
    const __nv_bfloat16 h = __float2bfloat16(v);
    hi[(size_t)nn * K + kk] = h;
    lo[(size_t)nn * K + kk] = __float2bfloat16(v - __bfloat162float(h));
}

// V transpose (hi+lo fused): qkv[token][2048 + h*64 + d] -> vt[bh*64 + d][j]
__global__ void vtrans_kernel(const __nv_bfloat16* __restrict__ qkvhi,
                              const __nv_bfloat16* __restrict__ qkvlo,
                              __nv_bfloat16* __restrict__ vthi,
                              __nv_bfloat16* __restrict__ vtlo)
{
    __shared__ __nv_bfloat16 th[32][33];
    __shared__ __nv_bfloat16 tl[32][33];
    const int bh = blockIdx.z;
    const int b  = bh >> 4;
    const int h  = bh & 15;
    const int j0 = blockIdx.x * 32;
    const int d0 = blockIdx.y * 32;
    const size_t src =
        (size_t)(b * SEQ + j0 + threadIdx.y) * QKVN + 2048 + h * DH + d0 + threadIdx.x;
    th[threadIdx.y][threadIdx.x] = qkvhi[src];
    tl[threadIdx.y][threadIdx.x] = qkvlo[src];
    __syncthreads();
    const size_t dst = ((size_t)bh * DH + d0 + threadIdx.y) * SEQ + j0 + threadIdx.x;
    vthi[dst] = th[threadIdx.x][threadIdx.y];
    vtlo[dst] = tl[threadIdx.x][threadIdx.y];
}

// ---------------- flash attention on tensor cores ----------------------------
#define LDK 72
#define LDV 136
#define KSTG (128 * LDK)
#define VSTG (DH * LDV)
#define STG_ELEMS (2 * KSTG + 2 * VSTG)
#define ASMEM (2 * STG_ELEMS * 2)
#define NITER (SEQ / 128)

__global__ __launch_bounds__(256, 1) void flash_mma(
    const __nv_bfloat16* __restrict__ qkvhi,
    const __nv_bfloat16* __restrict__ qkvlo,
    const __nv_bfloat16* __restrict__ vthi,
    const __nv_bfloat16* __restrict__ vtlo,
    __nv_bfloat16* __restrict__ ahi,
    __nv_bfloat16* __restrict__ alo)
{
    extern __shared__ __nv_bfloat16 smb[];

    const int tid  = threadIdx.x;
    const int lane = tid & 31;
    const int w    = tid >> 5;
    const int r    = lane >> 2;
    const int cq   = (lane & 3) * 2;
    const int h    = blockIdx.y;
    const int b    = blockIdx.z;
    const int q0   = blockIdx.x * 128;
    const size_t tb = (size_t)b * SEQ;
    const int bh   = b * HEADS + h;

    // ldmatrix B-fragment lane offsets (row within 8-row group + col offset)
    const int f_row  = lane & 7;
    const int f_koff = ((lane >> 3) & 1) * 8 + ((lane >> 4) & 1) * 16;

#define A_ISSUE(it, st) do {                                                     \
    const int _j0 = (it) * 128;                                                  \
    __nv_bfloat16* _khi = smb + (st) * STG_ELEMS;                                \
    __nv_bfloat16* _klo = _khi + KSTG;                                           \
    __nv_bfloat16* _vhi = _klo + KSTG;                                           \
    __nv_bfloat16* _vlo = _vhi + VSTG;                                           \
    for (int sg = tid; sg < 1024; sg += 256) {                                   \
        const int _j = sg >> 3, _so = (sg & 7) * 8;                              \
        const size_t _src = (tb + _j0 + _j) * QKVN + DIMM + h * DH + _so;        \
        cpasync16(smem_u32(_khi + _j * LDK + _so), qkvhi + _src);                \
        cpasync16(smem_u32(_klo + _j * LDK + _so), qkvlo + _src);                \
    }                                                                            \
    for (int sg = tid; sg < 1024; sg += 256) {                                   \
        const int _d = sg >> 4, _so = (sg & 15) * 8;                             \
        const size_t _src = ((size_t)bh * DH + _d) * SEQ + _j0 + _so;            \
        cpasync16(smem_u32(_vhi + _d * LDV + _so), vthi + _src);                 \
        cpasync16(smem_u32(_vlo + _d * LDV + _so), vtlo + _src);                 \
    }                                                                            \
    asm volatile("cp.async.commit_group;" ::: "memory");                         \
} while (0)

    // ---- Q fragments (loaded once; q pre-scaled by 0.125) ----
    uint32_t qh[4][4], ql[4][4];
    {
        const __nv_bfloat16* qbh = qkvhi + (tb + q0 + w * 16) * QKVN + h * DH;
        const __nv_bfloat16* qbl = qkvlo + (tb + q0 + w * 16) * QKVN + h * DH;
#pragma unroll
        for (int g = 0; g < 4; g++) {
            qh[g][0] = *(const uint32_t*)(qbh + (size_t)r * QKVN + g * 16 + cq);
            qh[g][1] = *(const uint32_t*)(qbh + (size_t)(r + 8) * QKVN + g * 16 + cq);
            qh[g][2] = *(const uint32_t*)(qbh + (size_t)r * QKVN + g * 16 + cq + 8);
            qh[g][3] = *(const uint32_t*)(qbh + (size_t)(r + 8) * QKVN + g * 16 + cq + 8);
            ql[g][0] = *(const uint32_t*)(qbl + (size_t)r * QKVN + g * 16 + cq);
            ql[g][1] = *(const uint32_t*)(qbl + (size_t)(r + 8) * QKVN + g * 16 + cq);
            ql[g][2] = *(const uint32_t*)(qbl + (size_t)r * QKVN + g * 16 + cq + 8);
            ql[g][3] = *(const uint32_t*)(qbl + (size_t)(r + 8) * QKVN + g * 16 + cq + 8);
        }
    }

    float m0 = -1e30f, m1 = -1e30f, l0 = 0.0f, l1 = 0.0f;
    float o[8][4];
#pragma unroll
    for (int nt = 0; nt < 8; nt++)
#pragma unroll
        for (int i = 0; i < 4; i++) o[nt][i] = 0.0f;

    A_ISSUE(0, 0);

    for (int it = 0; it < NITER; it++) {
        const int st = it & 1;
        if (it + 1 < NITER) {
            A_ISSUE(it + 1, st ^ 1);
            asm volatile("cp.async.wait_group 1;" ::: "memory");
        } else {
            asm volatile("cp.async.wait_group 0;" ::: "memory");
        }
        __syncthreads();

        const __nv_bfloat16* khi = smb + st * STG_ELEMS;
        const __nv_bfloat16* klo = khi + KSTG;
        const __nv_bfloat16* vhi = klo + KSTG;
        const __nv_bfloat16* vlo = vhi + VSTG;
        const uint32_t khb = smem_u32(khi), klb = smem_u32(klo);
        const uint32_t vhb = smem_u32(vhi), vlb = smem_u32(vlo);

        // ---- S = Q K^T (3-term hi/lo) via ldmatrix ----
        float s[16][4];
#pragma unroll
        for (int nt = 0; nt < 16; nt++)
#pragma unroll
            for (int i = 0; i < 4; i++) s[nt][i] = 0.0f;

#pragma unroll
        for (int nt = 0; nt < 16; nt++) {
            const uint32_t rowoff = ((nt * 8 + f_row) * LDK + f_koff) * 2;
            uint32_t kh4[2][4], kl4[2][4];
#pragma unroll
            for (int gp = 0; gp < 2; gp++) {
                ldsm4(kh4[gp], khb + rowoff + gp * 64);   // 32 bf16 = 64 B
                ldsm4(kl4[gp], klb + rowoff + gp * 64);
            }
#pragma unroll
            for (int g = 0; g < 4; g++) {
                const uint32_t* kh_ = &kh4[g >> 1][(g & 1) * 2];
                const uint32_t* kl_ = &kl4[g >> 1][(g & 1) * 2];
                mma16816(s[nt], qh[g], kh_);
                mma16816(s[nt], ql[g], kh_);
                mma16816(s[nt], qh[g], kl_);
            }
        }

        // ---- online softmax (rows r and r+8) ----
        float mx0 = -1e30f, mx1 = -1e30f;
#pragma unroll
        for (int nt = 0; nt < 16; nt++) {
            mx0 = fmaxf(mx0, fmaxf(s[nt][0], s[nt][1]));
            mx1 = fmaxf(mx1, fmaxf(s[nt][2], s[nt][3]));
        }
        mx0 = fmaxf(mx0, __shfl_xor_sync(0xffffffffu, mx0, 1));
        mx0 = fmaxf(mx0, __shfl_xor_sync(0xffffffffu, mx0, 2));
        mx1 = fmaxf(mx1, __shfl_xor_sync(0xffffffffu, mx1, 1));
        mx1 = fmaxf(mx1, __shfl_xor_sync(0xffffffffu, mx1, 2));
        const float mn0 = fmaxf(m0, mx0);
        const float mn1 = fmaxf(m1, mx1);
        const float al0 = __expf(m0 - mn0);
        const float al1 = __expf(m1 - mn1);
        m0 = mn0; m1 = mn1;
        float rs0 = 0.0f, rs1 = 0.0f;
#pragma unroll
        for (int nt = 0; nt < 16; nt++) {
            s[nt][0] = __expf(s[nt][0] - mn0);
            s[nt][1] = __expf(s[nt][1] - mn0);
            s[nt][2] = __expf(s[nt][2] - mn1);
            s[nt][3] = __expf(s[nt][3] - mn1);
            rs0 += s[nt][0] + s[nt][1];
            rs1 += s[nt][2] + s[nt][3];
        }
        rs0 += __shfl_xor_sync(0xffffffffu, rs0, 1);
        rs0 += __shfl_xor_sync(0xffffffffu, rs0, 2);
        rs1 += __shfl_xor_sync(0xffffffffu, rs1, 1);
        rs1 += __shfl_xor_sync(0xffffffffu, rs1, 2);
        l0 = l0 * al0 + rs0;
        l1 = l1 * al1 + rs1;
#pragma unroll
        for (int nt = 0; nt < 8; nt++) {
            o[nt][0] *= al0; o[nt][1] *= al0;
            o[nt][2] *= al1; o[nt][3] *= al1;
        }

        // ---- pack P (hi/lo) as A-fragments ----
        uint32_t ph[8][4], pl[8][4];
#pragma unroll
        for (int jg = 0; jg < 8; jg++) {
            pack2(s[2 * jg    ][0], s[2 * jg    ][1], ph[jg][0], pl[jg][0]);
            pack2(s[2 * jg    ][2], s[2 * jg    ][3], ph[jg][1], pl[jg][1]);
            pack2(s[2 * jg + 1][0], s[2 * jg + 1][1], ph[jg][2], pl[jg][2]);
            pack2(s[2 * jg + 1][2], s[2 * jg + 1][3], ph[jg][3], pl[jg][3]);
        }

        // ---- O += P V (3-term hi/lo) via ldmatrix, V is [d][j] ----
#pragma unroll
        for (int nt = 0; nt < 8; nt++) {
            const uint32_t rowoff = ((nt * 8 + f_row) * LDV + f_koff) * 2;
#pragma unroll
            for (int jp = 0; jp < 4; jp++) {
                uint32_t vh4[4], vl4[4];
                ldsm4(vh4, vhb + rowoff + jp * 64);
                ldsm4(vl4, vlb + rowoff + jp * 64);
                mma16816(o[nt], ph[2 * jp    ], vh4 + 0);
                mma16816(o[nt], pl[2 * jp    ], vh4 + 0);
                mma16816(o[nt], ph[2 * jp    ], vl4 + 0);
                mma16816(o[nt], ph[2 * jp + 1], vh4 + 2);
                mma16816(o[nt], pl[2 * jp + 1], vh4 + 2);
                mma16816(o[nt], ph[2 * jp + 1], vl4 + 2);
            }
        }
        __syncthreads();
    }

    // ---- epilogue ----
    const float inv0 = 1.0f / l0;
    const float inv1 = 1.0f / l1;
#pragma unroll
    for (int nt = 0; nt < 8; nt++) {
        const size_t b0 = (tb + q0 + w * 16 + r) * DIMM + h * DH + nt * 8 + cq;
        const size_t b1 = (tb + q0 + w * 16 + r + 8) * DIMM + h * DH + nt * 8 + cq;
        uint32_t H, L;
        pack2(o[nt][0] * inv0, o[nt][1] * inv0, H, L);
        *(uint32_t*)(ahi + b0) = H;
        *(uint32_t*)(alo + b0) = L;
        pack2(o[nt][2] * inv1, o[nt][3] * inv1, H, L);
        *(uint32_t*)(ahi + b1) = H;
        *(uint32_t*)(alo + b1) = L;
    }
}

// ---------------- host ----------------
extern "C" void kernel_launch(void* const* d_in, const int* in_sizes, int n_in,
                              void* d_out, int out_size)
{
    const float* x    = (const float*)d_in[0];
    const float* wqkv = (const float*)d_in[1];
    const float* wout = (const float*)d_in[2];
    const float* bout = (const float*)d_in[3];
    float* out = (float*)d_out;

    void *xhi_p, *xlo_p, *w1h_p, *w1l_p, *w2h_p, *w2l_p;
    void *qh_p, *ql_p, *vth_p, *vtl_p, *ahi_p, *alo_p;
    cudaGetSymbolAddress(&xhi_p, g_xhi);   cudaGetSymbolAddress(&xlo_p, g_xlo);
    cudaGetSymbolAddress(&w1h_p, g_w1hi);  cudaGetSymbolAddress(&w1l_p, g_w1lo);
    cudaGetSymbolAddress(&w2h_p, g_w2hi);  cudaGetSymbolAddress(&w2l_p, g_w2lo);
    cudaGetSymbolAddress(&qh_p,  g_qkvhi); cudaGetSymbolAddress(&ql_p,  g_qkvlo);
    cudaGetSymbolAddress(&vth_p, g_vthi);  cudaGetSymbolAddress(&vtl_p, g_vtlo);
    cudaGetSymbolAddress(&ahi_p, g_ahi);   cudaGetSymbolAddress(&alo_p, g_alo);

    cudaFuncSetAttribute(flash_mma, cudaFuncAttributeMaxDynamicSharedMemorySize, ASMEM);

    // 1) split x -> bf16 hi/lo
    {
        const int n4 = TOKENS * DIMM / 4;
        split_kernel<<<(n4 + 255) / 256, 256>>>((const float4*)x,
            (__nv_bfloat162*)xhi_p, (__nv_bfloat162*)xlo_p, n4);
    }
    // 2) transpose+split weights
    tsplit_kernel<<<dim3(QKVN / 32, DIMM / 32), dim3(32, 32)>>>(
        wqkv, (__nv_bfloat16*)w1h_p, (__nv_bfloat16*)w1l_p, DIMM, QKVN);
    tsplit_kernel<<<dim3(DIMM / 32, DIMM / 32), dim3(32, 32)>>>(
        wout, (__nv_bfloat16*)w2h_p, (__nv_bfloat16*)w2l_p, DIMM, DIMM);

    // 3) qkv = x @ w_qkv -> hi/lo bf16, q pre-scaled by 0.125
    gemm_mma<<<dim3(QKVN / 128, TOKENS / 128), 256>>>(
        (const __nv_bfloat16*)xhi_p, (const __nv_bfloat16*)xlo_p,
        (const __nv_bfloat16*)w1h_p, (const __nv_bfloat16*)w1l_p,
        nullptr, nullptr,
        (__nv_bfloat16*)qh_p, (__nv_bfloat16*)ql_p, QKVN, DIMM);

    // 4) transpose V -> [bh][d][j] (hi+lo fused)
    vtrans_kernel<<<dim3(SEQ / 32, DH / 32, BATCH * HEADS), dim3(32, 32)>>>(
        (const __nv_bfloat16*)qh_p, (const __nv_bfloat16*)ql_p,
        (__nv_bfloat16*)vth_p, (__nv_bfloat16*)vtl_p);

    // 5) flash attention on tensor cores
    flash_mma<<<dim3(SEQ / 128, HEADS, BATCH), 256, ASMEM>>>(
        (const __nv_bfloat16*)qh_p, (const __nv_bfloat16*)ql_p,
        (const __nv_bfloat16*)vth_p, (const __nv_bfloat16*)vtl_p,
        (__nv_bfloat16*)ahi_p, (__nv_bfloat16*)alo_p);

    // 6) out = attn @ w_out + b_out (fp32)
    gemm_mma<<<dim3(DIMM / 128, TOKENS / 128), 256>>>(
        (const __nv_bfloat16*)ahi_p, (const __nv_bfloat16*)alo_p,
        (const __nv_bfloat16*)w2h_p, (const __nv_bfloat16*)w2l_p,
        bout, out, nullptr, nullptr, DIMM, 0);
}